// round 6
// baseline (speedup 1.0000x reference)
#include <cuda_runtime.h>

#define FH 50
#define FW 50
#define CH 256
#define BATCH 4
#define NROI 1024
#define HOUT 7
#define WOUT 7
#define NBIN (HOUT*WOUT)
#define RATIO (1.0f/32.0f)
#define NGRP 4
#define TPB (128*NGRP)
#define HW (FH*FW)

// smem: tile[CH*NBIN] floats (50176B, 16B-aligned) + 4 geo arrays of NBIN*16B
#define SMEM_BYTES (CH*NBIN*4 + 4*NBIN*16)

// Features transposed to BHWC so channel reads are contiguous.
__device__ float g_feats[BATCH * HW * CH];

// ---------------------------------------------------------------------------
// Kernel 1: BCHW -> BHWC, classic 32x32 smem-tiled transpose per batch.
// Per batch: in = M[C][HW], out = M^T[HW][C]. Coalesced on both sides.
// grid (cTiles=8, pTiles=79, batch=4), block (32, 8).
// ---------------------------------------------------------------------------
__global__ void transpose_feats_kernel(const float* __restrict__ in) {
    __shared__ float t[32][33];
    int b  = blockIdx.z;
    int c0 = blockIdx.x * 32;
    int p0 = blockIdx.y * 32;
    const float* src = in + (size_t)b * CH * HW;
    float* dst = g_feats + (size_t)b * HW * CH;

    int p = p0 + threadIdx.x;
#pragma unroll
    for (int i = 0; i < 32; i += 8) {
        int c = c0 + threadIdx.y + i;
        if (p < HW)   // c < CH always (256 = 8*32)
            t[threadIdx.y + i][threadIdx.x] = src[(size_t)c * HW + p];
    }
    __syncthreads();
    int c = c0 + threadIdx.x;
#pragma unroll
    for (int i = 0; i < 32; i += 8) {
        int pp = p0 + threadIdx.y + i;
        if (pp < HW)
            dst[(size_t)pp * CH + c] = t[threadIdx.x][threadIdx.y + i];
    }
}

// bilinear + max for one sample (float2 = 2 channels)
#define SAMPLE(m0, m1, q00, q01, q10, q11, xh, xl, yb, yt)          \
    do {                                                            \
        float top0 = (xh) * (q01).x + (xl) * (q00).x;               \
        float bot0 = (xh) * (q11).x + (xl) * (q10).x;               \
        float top1 = (xh) * (q01).y + (xl) * (q00).y;               \
        float bot1 = (xh) * (q11).y + (xl) * (q10).y;               \
        m0 = fmaxf(m0, (yb) * bot0 + (yt) * top0);                  \
        m1 = fmaxf(m1, (yb) * bot1 + (yt) * top1);                  \
    } while (0)

// ---------------------------------------------------------------------------
// Kernel 2: RoIAlign. One block per roi, 512 threads, 3 CTAs/SM target.
//   Phase A: threads 0..48 compute per-bin geometry into smem once.
//   Phase B: tid&127 = channel pair, tid>>7 = bin group; corner-set dedup
//            via warp-uniform branches (2x2 samples usually share cells).
//   Phase C: coalesced float4 flush of the staged (C,49) tile.
// ---------------------------------------------------------------------------
__global__ __launch_bounds__(TPB, 3)
void roialign_kernel(const float* __restrict__ rois,
                     float* __restrict__ out) {
    extern __shared__ float smem[];
    float*  tile   = smem;                              // [CH][NBIN]
    int4*   g_rows = (int4*)(smem + CH * NBIN);         // [NBIN] yl0,yh0,yl1,yh1 (row offs, float2 units)
    int4*   g_cols = g_rows + NBIN;                     // [NBIN] xl0,xh0,xl1,xh1 (col offs, float2 units)
    float4* g_wy   = (float4*)(g_cols + NBIN);          // [NBIN] wyb0,wyt0,wyb1,wyt1 (0 if invalid)
    float4* g_wx   = g_wy + NBIN;                       // [NBIN] wxh0,wxl0,wxh1,wxl1

    int r   = blockIdx.x;
    int tid = threadIdx.x;

    int b = (int)__ldg(&rois[r * 5 + 0]);
    const float2* fbase = (const float2*)g_feats + (size_t)b * HW * (CH / 2);

    // ---- Phase A ----
    if (tid < NBIN) {
        float bx1 = fminf(fmaxf(__ldg(&rois[r * 5 + 1]) * RATIO, 0.f), (float)FW);
        float by1 = fminf(fmaxf(__ldg(&rois[r * 5 + 2]) * RATIO, 0.f), (float)FH);
        float bx2 = fminf(fmaxf(__ldg(&rois[r * 5 + 3]) * RATIO, 0.f), (float)FW);
        float by2 = fminf(fmaxf(__ldg(&rois[r * 5 + 4]) * RATIO, 0.f), (float)FH);
        bool roi_valid = (bx2 - bx1 > 0.f) && (by2 - by1 > 0.f);
        float bin_w = (bx2 - bx1) * (1.0f / WOUT);
        float bin_h = (by2 - by1) * (1.0f / HOUT);

        int i = tid / WOUT;
        int j = tid - i * WOUT;

        float y1u = by1 + (float)i * bin_h;
        float y1b = fminf(fmaxf(y1u, 0.f), (float)FH);
        float y2b = fminf(fmaxf(y1u + bin_h, 0.f), (float)FH);
        float x1u = bx1 + (float)j * bin_w;
        float x1b = fminf(fmaxf(x1u, 0.f), (float)FW);
        float x2b = fminf(fmaxf(x1u + bin_w, 0.f), (float)FW);
        bool valid = roi_valid && (x2b > x1b) && (y2b > y1b);
        float vscale = valid ? 1.f : 0.f;

        int   rowi[4], coli[4];
        float wyv[4], wxv[4];
#pragma unroll
        for (int t = 0; t < 2; t++) {
            float py = y1b + ((float)t + 0.5f) * (bin_h * 0.5f);
            float yl = fminf(fmaxf(floorf(py), 0.f), (float)(FH - 1));
            int ylI = (int)yl;
            int yhI = min(ylI + 1, FH - 1);
            rowi[2 * t + 0] = ylI * FW * (CH / 2);
            rowi[2 * t + 1] = yhI * FW * (CH / 2);
            wyv[2 * t + 0] = (py - yl) * vscale;          // wyb (zeroed if invalid)
            wyv[2 * t + 1] = ((float)yhI - py) * vscale;  // wyt (NOT 1-wyb)

            float px = x1b + ((float)t + 0.5f) * (bin_w * 0.5f);
            float xl = fminf(fmaxf(floorf(px), 0.f), (float)(FW - 1));
            int xlI = (int)xl;
            int xhI = min(xlI + 1, FW - 1);
            coli[2 * t + 0] = xlI * (CH / 2);
            coli[2 * t + 1] = xhI * (CH / 2);
            wxv[2 * t + 0] = px - xl;          // wxh
            wxv[2 * t + 1] = (float)xhI - px;  // wxl
        }
        g_rows[tid] = make_int4(rowi[0], rowi[1], rowi[2], rowi[3]);
        g_cols[tid] = make_int4(coli[0], coli[1], coli[2], coli[3]);
        g_wy[tid]   = make_float4(wyv[0], wyv[1], wyv[2], wyv[3]);
        g_wx[tid]   = make_float4(wxv[0], wxv[1], wxv[2], wxv[3]);
    }
    __syncthreads();

    // ---- Phase B ----
    int c2  = tid & 127;       // channel pair 0..127
    int grp = tid >> 7;        // bin group 0..3
    const float2* fb2 = fbase + c2;

    for (int k = grp; k < NBIN; k += NGRP) {
        int4   rw = g_rows[k];
        int4   cl = g_cols[k];
        float4 wy = g_wy[k];
        float4 wx = g_wx[k];
        bool sameX = (cl.z == cl.x) && (cl.w == cl.y);
        bool sameY = (rw.z == rw.x) && (rw.w == rw.y);

        // Corner set A: rows pair0 x cols pair0 (always needed)
        float2 a00 = fb2[rw.x + cl.x];
        float2 a01 = fb2[rw.x + cl.y];
        float2 a10 = fb2[rw.y + cl.x];
        float2 a11 = fb2[rw.y + cl.y];

        float v0 = wx.x * a01.x + wx.y * a00.x;   // sample(0,0) top
        float w0 = wx.x * a11.x + wx.y * a10.x;   // bot
        float v1 = wx.x * a01.y + wx.y * a00.y;
        float w1 = wx.x * a11.y + wx.y * a10.y;
        float m0 = wy.x * w0 + wy.y * v0;
        float m1 = wy.x * w1 + wy.y * v1;

        // Corner set B: rows pair0 x cols pair1
        float2 b00, b01, b10, b11;
        if (sameX) { b00 = a00; b01 = a01; b10 = a10; b11 = a11; }
        else {
            b00 = fb2[rw.x + cl.z]; b01 = fb2[rw.x + cl.w];
            b10 = fb2[rw.y + cl.z]; b11 = fb2[rw.y + cl.w];
        }
        SAMPLE(m0, m1, b00, b01, b10, b11, wx.z, wx.w, wy.x, wy.y);

        // Corner sets C (rows pair1 x cols pair0) and D (rows pair1 x cols pair1)
        float2 c00, c01, c10, c11, d00, d01, d10, d11;
        if (sameY) {
            c00 = a00; c01 = a01; c10 = a10; c11 = a11;
            d00 = b00; d01 = b01; d10 = b10; d11 = b11;
        } else {
            c00 = fb2[rw.z + cl.x]; c01 = fb2[rw.z + cl.y];
            c10 = fb2[rw.w + cl.x]; c11 = fb2[rw.w + cl.y];
            if (sameX) { d00 = c00; d01 = c01; d10 = c10; d11 = c11; }
            else {
                d00 = fb2[rw.z + cl.z]; d01 = fb2[rw.z + cl.w];
                d10 = fb2[rw.w + cl.z]; d11 = fb2[rw.w + cl.w];
            }
        }
        SAMPLE(m0, m1, c00, c01, c10, c11, wx.x, wx.y, wy.z, wy.w);
        SAMPLE(m0, m1, d00, d01, d10, d11, wx.z, wx.w, wy.z, wy.w);

        tile[(2 * c2 + 0) * NBIN + k] = m0;
        tile[(2 * c2 + 1) * NBIN + k] = m1;
    }
    __syncthreads();

    // ---- Phase C: tile[c*49 + k] is exactly (N,C,7,7) order for this roi ----
    float4* dst4       = (float4*)(out + (size_t)r * CH * NBIN);
    const float4* src4 = (const float4*)tile;
    for (int idx = tid; idx < CH * NBIN / 4; idx += blockDim.x)
        dst4[idx] = src4[idx];
}

extern "C" void kernel_launch(void* const* d_in, const int* in_sizes, int n_in,
                              void* d_out, int out_size) {
    const float* feats = (const float*)d_in[0];   // (4,256,50,50) f32
    const float* rois  = (const float*)d_in[1];   // (1024,5) f32
    float* out = (float*)d_out;                   // (1024,256,7,7) f32

    cudaFuncSetAttribute(roialign_kernel,
                         cudaFuncAttributeMaxDynamicSharedMemorySize, SMEM_BYTES);

    dim3 tgrid(CH / 32, (HW + 31) / 32, BATCH);
    dim3 tblk(32, 8);
    transpose_feats_kernel<<<tgrid, tblk>>>(feats);
    roialign_kernel<<<NROI, TPB, SMEM_BYTES>>>(rois, out);
}

// round 7
// speedup vs baseline: 1.5365x; 1.5365x over previous
#include <cuda_runtime.h>

#define FH 50
#define FW 50
#define CH 256
#define BATCH 4
#define NROI 1024
#define HOUT 7
#define WOUT 7
#define NBIN (HOUT*WOUT)
#define RATIO (1.0f/32.0f)
#define NGRP 4
#define TPB (128*NGRP)
#define HW (FH*FW)

// smem: tile[CH*NBIN] floats (50176B, 16B-aligned) + 4 geo arrays of NBIN*16B
#define SMEM_BYTES (CH*NBIN*4 + 4*NBIN*16)

// Features transposed to BHWC so channel reads are contiguous.
__device__ float g_feats[BATCH * HW * CH];

// ---------------------------------------------------------------------------
// Kernel 1: BCHW -> BHWC, classic 32x32 smem-tiled transpose per batch.
// Per batch: in = M[C][HW], out = M^T[HW][C]. Coalesced on both sides.
// grid (cTiles=8, pTiles=79, batch=4), block (32, 8).  (~2.3us measured)
// ---------------------------------------------------------------------------
__global__ void transpose_feats_kernel(const float* __restrict__ in) {
    __shared__ float t[32][33];
    int b  = blockIdx.z;
    int c0 = blockIdx.x * 32;
    int p0 = blockIdx.y * 32;
    const float* src = in + (size_t)b * CH * HW;
    float* dst = g_feats + (size_t)b * HW * CH;

    int p = p0 + threadIdx.x;
#pragma unroll
    for (int i = 0; i < 32; i += 8) {
        int c = c0 + threadIdx.y + i;
        if (p < HW)   // c < CH always (256 = 8*32)
            t[threadIdx.y + i][threadIdx.x] = src[(size_t)c * HW + p];
    }
    __syncthreads();
    int c = c0 + threadIdx.x;
#pragma unroll
    for (int i = 0; i < 32; i += 8) {
        int pp = p0 + threadIdx.y + i;
        if (pp < HW)
            dst[(size_t)pp * CH + c] = t[threadIdx.x][threadIdx.y + i];
    }
}

// bilinear + max for one sample (float2 = 2 channels)
#define SAMPLE(m0, m1, q00, q01, q10, q11, xh, xl, yb, yt)          \
    do {                                                            \
        float top0 = (xh) * (q01).x + (xl) * (q00).x;               \
        float bot0 = (xh) * (q11).x + (xl) * (q10).x;               \
        float top1 = (xh) * (q01).y + (xl) * (q00).y;               \
        float bot1 = (xh) * (q11).y + (xl) * (q10).y;               \
        m0 = fmaxf(m0, (yb) * bot0 + (yt) * top0);                  \
        m1 = fmaxf(m1, (yb) * bot1 + (yt) * top1);                  \
    } while (0)

// ---------------------------------------------------------------------------
// Kernel 2: RoIAlign. One block per roi, 512 threads, EXACTLY 2 CTAs/SM:
// smem 2x53.4KB leaves ~121KB L1D, which covers two roi footprints (R6 showed
// 3 CTAs/SM shrinks L1D to ~68KB and collapses into L2 latency).
//   Phase A: threads 0..48 compute per-bin geometry into smem once.
//   Phase B: tid&127 = channel pair, tid>>7 = bin group; corner-set dedup
//            via warp-uniform branches (2x2 samples usually share cells).
//   Phase C: coalesced float4 flush of the staged (C,49) tile.
// ---------------------------------------------------------------------------
__global__ __launch_bounds__(TPB, 2)
void roialign_kernel(const float* __restrict__ rois,
                     float* __restrict__ out) {
    extern __shared__ float smem[];
    float*  tile   = smem;                              // [CH][NBIN]
    int4*   g_rows = (int4*)(smem + CH * NBIN);         // [NBIN] yl0,yh0,yl1,yh1 (row offs, float2 units)
    int4*   g_cols = g_rows + NBIN;                     // [NBIN] xl0,xh0,xl1,xh1 (col offs, float2 units)
    float4* g_wy   = (float4*)(g_cols + NBIN);          // [NBIN] wyb0,wyt0,wyb1,wyt1 (0 if invalid)
    float4* g_wx   = g_wy + NBIN;                       // [NBIN] wxh0,wxl0,wxh1,wxl1

    int r   = blockIdx.x;
    int tid = threadIdx.x;

    int b = (int)__ldg(&rois[r * 5 + 0]);
    const float2* fbase = (const float2*)g_feats + (size_t)b * HW * (CH / 2);

    // ---- Phase A ----
    if (tid < NBIN) {
        float bx1 = fminf(fmaxf(__ldg(&rois[r * 5 + 1]) * RATIO, 0.f), (float)FW);
        float by1 = fminf(fmaxf(__ldg(&rois[r * 5 + 2]) * RATIO, 0.f), (float)FH);
        float bx2 = fminf(fmaxf(__ldg(&rois[r * 5 + 3]) * RATIO, 0.f), (float)FW);
        float by2 = fminf(fmaxf(__ldg(&rois[r * 5 + 4]) * RATIO, 0.f), (float)FH);
        bool roi_valid = (bx2 - bx1 > 0.f) && (by2 - by1 > 0.f);
        float bin_w = (bx2 - bx1) * (1.0f / WOUT);
        float bin_h = (by2 - by1) * (1.0f / HOUT);

        int i = tid / WOUT;
        int j = tid - i * WOUT;

        float y1u = by1 + (float)i * bin_h;
        float y1b = fminf(fmaxf(y1u, 0.f), (float)FH);
        float y2b = fminf(fmaxf(y1u + bin_h, 0.f), (float)FH);
        float x1u = bx1 + (float)j * bin_w;
        float x1b = fminf(fmaxf(x1u, 0.f), (float)FW);
        float x2b = fminf(fmaxf(x1u + bin_w, 0.f), (float)FW);
        bool valid = roi_valid && (x2b > x1b) && (y2b > y1b);
        float vscale = valid ? 1.f : 0.f;

        int   rowi[4], coli[4];
        float wyv[4], wxv[4];
#pragma unroll
        for (int t = 0; t < 2; t++) {
            float py = y1b + ((float)t + 0.5f) * (bin_h * 0.5f);
            float yl = fminf(fmaxf(floorf(py), 0.f), (float)(FH - 1));
            int ylI = (int)yl;
            int yhI = min(ylI + 1, FH - 1);
            rowi[2 * t + 0] = ylI * FW * (CH / 2);
            rowi[2 * t + 1] = yhI * FW * (CH / 2);
            wyv[2 * t + 0] = (py - yl) * vscale;          // wyb (zeroed if invalid)
            wyv[2 * t + 1] = ((float)yhI - py) * vscale;  // wyt (NOT 1-wyb)

            float px = x1b + ((float)t + 0.5f) * (bin_w * 0.5f);
            float xl = fminf(fmaxf(floorf(px), 0.f), (float)(FW - 1));
            int xlI = (int)xl;
            int xhI = min(xlI + 1, FW - 1);
            coli[2 * t + 0] = xlI * (CH / 2);
            coli[2 * t + 1] = xhI * (CH / 2);
            wxv[2 * t + 0] = px - xl;          // wxh
            wxv[2 * t + 1] = (float)xhI - px;  // wxl
        }
        g_rows[tid] = make_int4(rowi[0], rowi[1], rowi[2], rowi[3]);
        g_cols[tid] = make_int4(coli[0], coli[1], coli[2], coli[3]);
        g_wy[tid]   = make_float4(wyv[0], wyv[1], wyv[2], wyv[3]);
        g_wx[tid]   = make_float4(wxv[0], wxv[1], wxv[2], wxv[3]);
    }
    __syncthreads();

    // ---- Phase B ----
    int c2  = tid & 127;       // channel pair 0..127
    int grp = tid >> 7;        // bin group 0..3
    const float2* fb2 = fbase + c2;

    for (int k = grp; k < NBIN; k += NGRP) {
        int4   rw = g_rows[k];
        int4   cl = g_cols[k];
        float4 wy = g_wy[k];
        float4 wx = g_wx[k];
        bool sameX = (cl.z == cl.x) && (cl.w == cl.y);
        bool sameY = (rw.z == rw.x) && (rw.w == rw.y);

        // Corner set A: rows pair0 x cols pair0 (always needed)
        float2 a00 = fb2[rw.x + cl.x];
        float2 a01 = fb2[rw.x + cl.y];
        float2 a10 = fb2[rw.y + cl.x];
        float2 a11 = fb2[rw.y + cl.y];

        float v0 = wx.x * a01.x + wx.y * a00.x;   // sample(0,0) top
        float w0 = wx.x * a11.x + wx.y * a10.x;   // bot
        float v1 = wx.x * a01.y + wx.y * a00.y;
        float w1 = wx.x * a11.y + wx.y * a10.y;
        float m0 = wy.x * w0 + wy.y * v0;
        float m1 = wy.x * w1 + wy.y * v1;

        // Corner set B: rows pair0 x cols pair1
        float2 b00, b01, b10, b11;
        if (sameX) { b00 = a00; b01 = a01; b10 = a10; b11 = a11; }
        else {
            b00 = fb2[rw.x + cl.z]; b01 = fb2[rw.x + cl.w];
            b10 = fb2[rw.y + cl.z]; b11 = fb2[rw.y + cl.w];
        }
        SAMPLE(m0, m1, b00, b01, b10, b11, wx.z, wx.w, wy.x, wy.y);

        // Corner sets C (rows pair1 x cols pair0) and D (rows pair1 x cols pair1)
        float2 c00, c01, c10, c11, d00, d01, d10, d11;
        if (sameY) {
            c00 = a00; c01 = a01; c10 = a10; c11 = a11;
            d00 = b00; d01 = b01; d10 = b10; d11 = b11;
        } else {
            c00 = fb2[rw.z + cl.x]; c01 = fb2[rw.z + cl.y];
            c10 = fb2[rw.w + cl.x]; c11 = fb2[rw.w + cl.y];
            if (sameX) { d00 = c00; d01 = c01; d10 = c10; d11 = c11; }
            else {
                d00 = fb2[rw.z + cl.z]; d01 = fb2[rw.z + cl.w];
                d10 = fb2[rw.w + cl.z]; d11 = fb2[rw.w + cl.w];
            }
        }
        SAMPLE(m0, m1, c00, c01, c10, c11, wx.x, wx.y, wy.z, wy.w);
        SAMPLE(m0, m1, d00, d01, d10, d11, wx.z, wx.w, wy.z, wy.w);

        tile[(2 * c2 + 0) * NBIN + k] = m0;
        tile[(2 * c2 + 1) * NBIN + k] = m1;
    }
    __syncthreads();

    // ---- Phase C: tile[c*49 + k] is exactly (N,C,7,7) order for this roi ----
    float4* dst4       = (float4*)(out + (size_t)r * CH * NBIN);
    const float4* src4 = (const float4*)tile;
    for (int idx = tid; idx < CH * NBIN / 4; idx += blockDim.x)
        dst4[idx] = src4[idx];
}

extern "C" void kernel_launch(void* const* d_in, const int* in_sizes, int n_in,
                              void* d_out, int out_size) {
    const float* feats = (const float*)d_in[0];   // (4,256,50,50) f32
    const float* rois  = (const float*)d_in[1];   // (1024,5) f32
    float* out = (float*)d_out;                   // (1024,256,7,7) f32

    cudaFuncSetAttribute(roialign_kernel,
                         cudaFuncAttributeMaxDynamicSharedMemorySize, SMEM_BYTES);

    dim3 tgrid(CH / 32, (HW + 31) / 32, BATCH);
    dim3 tblk(32, 8);
    transpose_feats_kernel<<<tgrid, tblk>>>(feats);
    roialign_kernel<<<NROI, TPB, SMEM_BYTES>>>(rois, out);
}

// round 8
// speedup vs baseline: 1.5436x; 1.0046x over previous
#include <cuda_runtime.h>

#define FH 50
#define FW 50
#define CH 256
#define BATCH 4
#define NROI 1024
#define HOUT 7
#define WOUT 7
#define NBIN (HOUT*WOUT)
#define RATIO (1.0f/32.0f)
#define NGRP 4
#define TPB (128*NGRP)
#define HW (FH*FW)

// smem: tile[CH*NBIN] f32 + 4 offset int4[NBIN] + 2 weight float4[NBIN] + flag int[NBIN]
#define SMEM_BYTES (CH*NBIN*4 + 4*NBIN*16 + 2*NBIN*16 + NBIN*4)

// Features transposed to BHWC so channel reads are contiguous.
__device__ float g_feats[BATCH * HW * CH];

// ---------------------------------------------------------------------------
// Kernel 1: BCHW -> BHWC, classic 32x32 smem-tiled transpose per batch.
// ---------------------------------------------------------------------------
__global__ void transpose_feats_kernel(const float* __restrict__ in) {
    __shared__ float t[32][33];
    int b  = blockIdx.z;
    int c0 = blockIdx.x * 32;
    int p0 = blockIdx.y * 32;
    const float* src = in + (size_t)b * CH * HW;
    float* dst = g_feats + (size_t)b * HW * CH;

    int p = p0 + threadIdx.x;
#pragma unroll
    for (int i = 0; i < 32; i += 8) {
        int c = c0 + threadIdx.y + i;
        if (p < HW)
            t[threadIdx.y + i][threadIdx.x] = src[(size_t)c * HW + p];
    }
    __syncthreads();
    int c = c0 + threadIdx.x;
#pragma unroll
    for (int i = 0; i < 32; i += 8) {
        int pp = p0 + threadIdx.y + i;
        if (pp < HW)
            dst[(size_t)pp * CH + c] = t[threadIdx.x][threadIdx.y + i];
    }
}

// bilinear + max for one sample (float2 = 2 channels)
#define SAMPLE(m0, m1, q00, q01, q10, q11, xh, xl, yb, yt)          \
    do {                                                            \
        float top0 = (xh) * (q01).x + (xl) * (q00).x;               \
        float bot0 = (xh) * (q11).x + (xl) * (q10).x;               \
        float top1 = (xh) * (q01).y + (xl) * (q00).y;               \
        float bot1 = (xh) * (q11).y + (xl) * (q10).y;               \
        m0 = fmaxf(m0, (yb) * bot0 + (yt) * top0);                  \
        m1 = fmaxf(m1, (yb) * bot1 + (yt) * top1);                  \
    } while (0)

// ---------------------------------------------------------------------------
// Kernel 2: RoIAlign. One block per roi, 512 threads, EXACTLY 2 CTAs/SM
// (3 CTAs shrinks the L1D carveout below the working set -> L2-bound, R6).
//   Phase A: threads 0..48 build per-bin COMBINED corner offsets (row+col
//            pre-summed, float2 units) for corner sets A/B/C/D, weights,
//            and sameX/sameY flags. Invalid bins get zeroed y-weights.
//   Phase B: tid&127 = channel pair, tid>>7 = bin group. Pure LDS + LDG +
//            FMA; corner sets deduped via warp-uniform flag branches, and
//            oB/oC/oD are only loaded when actually needed.
//   Phase C: coalesced float4 flush of the staged (C,49) tile.
// ---------------------------------------------------------------------------
__global__ __launch_bounds__(TPB, 2)
void roialign_kernel(const float* __restrict__ rois,
                     float* __restrict__ out) {
    extern __shared__ float smem[];
    float*  tile   = smem;                              // [CH][NBIN]
    int4*   g_offA = (int4*)(smem + CH * NBIN);         // [NBIN] a00,a01,a10,a11
    int4*   g_offB = g_offA + NBIN;
    int4*   g_offC = g_offB + NBIN;
    int4*   g_offD = g_offC + NBIN;
    float4* g_wy   = (float4*)(g_offD + NBIN);          // [NBIN] wyb0,wyt0,wyb1,wyt1 (0 if invalid)
    float4* g_wx   = g_wy + NBIN;                       // [NBIN] wxh0,wxl0,wxh1,wxl1
    int*    g_flag = (int*)(g_wx + NBIN);               // [NBIN] bit0 sameX, bit1 sameY

    int r   = blockIdx.x;
    int tid = threadIdx.x;

    int b = (int)__ldg(&rois[r * 5 + 0]);
    const float2* fbase = (const float2*)g_feats + (size_t)b * HW * (CH / 2);

    // ---- Phase A ----
    if (tid < NBIN) {
        float bx1 = fminf(fmaxf(__ldg(&rois[r * 5 + 1]) * RATIO, 0.f), (float)FW);
        float by1 = fminf(fmaxf(__ldg(&rois[r * 5 + 2]) * RATIO, 0.f), (float)FH);
        float bx2 = fminf(fmaxf(__ldg(&rois[r * 5 + 3]) * RATIO, 0.f), (float)FW);
        float by2 = fminf(fmaxf(__ldg(&rois[r * 5 + 4]) * RATIO, 0.f), (float)FH);
        bool roi_valid = (bx2 - bx1 > 0.f) && (by2 - by1 > 0.f);
        float bin_w = (bx2 - bx1) * (1.0f / WOUT);
        float bin_h = (by2 - by1) * (1.0f / HOUT);

        int i = tid / WOUT;
        int j = tid - i * WOUT;

        float y1u = by1 + (float)i * bin_h;
        float y1b = fminf(fmaxf(y1u, 0.f), (float)FH);
        float y2b = fminf(fmaxf(y1u + bin_h, 0.f), (float)FH);
        float x1u = bx1 + (float)j * bin_w;
        float x1b = fminf(fmaxf(x1u, 0.f), (float)FW);
        float x2b = fminf(fmaxf(x1u + bin_w, 0.f), (float)FW);
        bool valid = roi_valid && (x2b > x1b) && (y2b > y1b);
        float vscale = valid ? 1.f : 0.f;

        int   rowi[4], coli[4];
        float wyv[4], wxv[4];
#pragma unroll
        for (int t = 0; t < 2; t++) {
            float py = y1b + ((float)t + 0.5f) * (bin_h * 0.5f);
            float yl = fminf(fmaxf(floorf(py), 0.f), (float)(FH - 1));
            int ylI = (int)yl;
            int yhI = min(ylI + 1, FH - 1);
            rowi[2 * t + 0] = ylI * FW * (CH / 2);
            rowi[2 * t + 1] = yhI * FW * (CH / 2);
            wyv[2 * t + 0] = (py - yl) * vscale;          // wyb (zeroed if invalid)
            wyv[2 * t + 1] = ((float)yhI - py) * vscale;  // wyt (NOT 1-wyb)

            float px = x1b + ((float)t + 0.5f) * (bin_w * 0.5f);
            float xl = fminf(fmaxf(floorf(px), 0.f), (float)(FW - 1));
            int xlI = (int)xl;
            int xhI = min(xlI + 1, FW - 1);
            coli[2 * t + 0] = xlI * (CH / 2);
            coli[2 * t + 1] = xhI * (CH / 2);
            wxv[2 * t + 0] = px - xl;          // wxh
            wxv[2 * t + 1] = (float)xhI - px;  // wxl
        }
        // Combined corner offsets: {rows pair} x {cols pair} per corner set.
        g_offA[tid] = make_int4(rowi[0] + coli[0], rowi[0] + coli[1],
                                rowi[1] + coli[0], rowi[1] + coli[1]);
        g_offB[tid] = make_int4(rowi[0] + coli[2], rowi[0] + coli[3],
                                rowi[1] + coli[2], rowi[1] + coli[3]);
        g_offC[tid] = make_int4(rowi[2] + coli[0], rowi[2] + coli[1],
                                rowi[3] + coli[0], rowi[3] + coli[1]);
        g_offD[tid] = make_int4(rowi[2] + coli[2], rowi[2] + coli[3],
                                rowi[3] + coli[2], rowi[3] + coli[3]);
        g_wy[tid] = make_float4(wyv[0], wyv[1], wyv[2], wyv[3]);
        g_wx[tid] = make_float4(wxv[0], wxv[1], wxv[2], wxv[3]);
        int sameX = (coli[2] == coli[0]) && (coli[3] == coli[1]);
        int sameY = (rowi[2] == rowi[0]) && (rowi[3] == rowi[1]);
        g_flag[tid] = sameX | (sameY << 1);
    }
    __syncthreads();

    // ---- Phase B ----
    int c2  = tid & 127;       // channel pair 0..127
    int grp = tid >> 7;        // bin group 0..3
    const float2* fb2 = fbase + c2;

    for (int k = grp; k < NBIN; k += NGRP) {
        int4   oA = g_offA[k];
        float4 wy = g_wy[k];
        float4 wx = g_wx[k];
        int    fl = g_flag[k];
        bool sameX = fl & 1;
        bool sameY = fl & 2;

        // Corner set A (always needed)
        float2 a00 = fb2[oA.x];
        float2 a01 = fb2[oA.y];
        float2 a10 = fb2[oA.z];
        float2 a11 = fb2[oA.w];

        float v0 = wx.x * a01.x + wx.y * a00.x;   // sample(0,0) top
        float w0 = wx.x * a11.x + wx.y * a10.x;   // bot
        float v1 = wx.x * a01.y + wx.y * a00.y;
        float w1 = wx.x * a11.y + wx.y * a10.y;
        float m0 = wy.x * w0 + wy.y * v0;
        float m1 = wy.x * w1 + wy.y * v1;

        // Corner set B: rows pair0 x cols pair1
        float2 b00, b01, b10, b11;
        if (sameX) { b00 = a00; b01 = a01; b10 = a10; b11 = a11; }
        else {
            int4 oB = g_offB[k];
            b00 = fb2[oB.x]; b01 = fb2[oB.y]; b10 = fb2[oB.z]; b11 = fb2[oB.w];
        }
        SAMPLE(m0, m1, b00, b01, b10, b11, wx.z, wx.w, wy.x, wy.y);

        // Corner sets C (rows pair1 x cols pair0) and D (rows pair1 x cols pair1)
        float2 c00, c01, c10, c11, d00, d01, d10, d11;
        if (sameY) {
            c00 = a00; c01 = a01; c10 = a10; c11 = a11;
            d00 = b00; d01 = b01; d10 = b10; d11 = b11;
        } else {
            int4 oC = g_offC[k];
            c00 = fb2[oC.x]; c01 = fb2[oC.y]; c10 = fb2[oC.z]; c11 = fb2[oC.w];
            if (sameX) { d00 = c00; d01 = c01; d10 = c10; d11 = c11; }
            else {
                int4 oD = g_offD[k];
                d00 = fb2[oD.x]; d01 = fb2[oD.y]; d10 = fb2[oD.z]; d11 = fb2[oD.w];
            }
        }
        SAMPLE(m0, m1, c00, c01, c10, c11, wx.x, wx.y, wy.z, wy.w);
        SAMPLE(m0, m1, d00, d01, d10, d11, wx.z, wx.w, wy.z, wy.w);

        tile[(2 * c2 + 0) * NBIN + k] = m0;
        tile[(2 * c2 + 1) * NBIN + k] = m1;
    }
    __syncthreads();

    // ---- Phase C: tile[c*49 + k] is exactly (N,C,7,7) order for this roi ----
    float4* dst4       = (float4*)(out + (size_t)r * CH * NBIN);
    const float4* src4 = (const float4*)tile;
    for (int idx = tid; idx < CH * NBIN / 4; idx += blockDim.x)
        dst4[idx] = src4[idx];
}

extern "C" void kernel_launch(void* const* d_in, const int* in_sizes, int n_in,
                              void* d_out, int out_size) {
    const float* feats = (const float*)d_in[0];   // (4,256,50,50) f32
    const float* rois  = (const float*)d_in[1];   // (1024,5) f32
    float* out = (float*)d_out;                   // (1024,256,7,7) f32

    cudaFuncSetAttribute(roialign_kernel,
                         cudaFuncAttributeMaxDynamicSharedMemorySize, SMEM_BYTES);

    dim3 tgrid(CH / 32, (HW + 31) / 32, BATCH);
    dim3 tblk(32, 8);
    transpose_feats_kernel<<<tgrid, tblk>>>(feats);
    roialign_kernel<<<NROI, TPB, SMEM_BYTES>>>(rois, out);
}